// round 10
// baseline (speedup 1.0000x reference)
#include <cuda_runtime.h>
#include <cuda_bf16.h>
#include <cstdint>

#define BB 128
#define SS 512
#define EE 512
#define HH 1024
#define VV 32000
#define NC 1000

typedef unsigned long long ull;

// ---------------- global scratch ----------------
__device__ float g_pt[(size_t)VV * 2048];          // token preacts (+bias)
__device__ unsigned char g_bfrag[64 * 131072];     // per-CTA recurrent B fragments (bf16)
__device__ unsigned char g_afrag[2 * 64 * 8 * 512];// h bf16 hi/lo A fragments: [pass][kt][mt][512B]
__device__ unsigned char g_efh[(size_t)2000 * 32 * 512];  // emb hi A-fragments
__device__ unsigned char g_efl[(size_t)2000 * 32 * 512];  // emb lo A-fragments
__device__ unsigned char g_wtfh[32 * 65536];       // Wtop hi B-fragments per col-tile
__device__ unsigned char g_wtfl[32 * 65536];       // Wtop lo B-fragments per col-tile
__device__ float g_wfc3[125 * 1024 * 8];           // classifier weights per block
__device__ float g_hf[BB * HH];                    // final hidden state fp32
__device__ unsigned g_bar;                         // grid barrier counter

// ---------------- helpers ----------------
__device__ __forceinline__ ull pack2(float a, float b) {
    ull r; asm("mov.b64 %0, {%1, %2};" : "=l"(r) : "f"(a), "f"(b)); return r;
}
__device__ __forceinline__ void unpack2(ull v, float& a, float& b) {
    asm("mov.b64 {%0, %1}, %2;" : "=f"(a), "=f"(b) : "l"(v));
}
__device__ __forceinline__ void ffma2(ull& d, ull a, ull b) {
    asm("fma.rn.f32x2 %0, %1, %2, %0;" : "+l"(d) : "l"(a), "l"(b));
}
__device__ __forceinline__ float4 ldcg4(const void* p) {
    float4 v;
    asm volatile("ld.global.cg.v4.f32 {%0,%1,%2,%3},[%4];"
                 : "=f"(v.x), "=f"(v.y), "=f"(v.z), "=f"(v.w) : "l"(p));
    return v;
}
__device__ __forceinline__ uint4 ldcgu4(const void* p) {
    uint4 v;
    asm volatile("ld.global.cg.v4.b32 {%0,%1,%2,%3},[%4];"
                 : "=r"(v.x), "=r"(v.y), "=r"(v.z), "=r"(v.w) : "l"(p));
    return v;
}
__device__ __forceinline__ void stcgu4(void* p, uint4 v) {
    asm volatile("st.global.cg.v4.b32 [%0],{%1,%2,%3,%4};"
                 :: "l"(p), "r"(v.x), "r"(v.y), "r"(v.z), "r"(v.w) : "memory");
}
__device__ __forceinline__ uint32_t bfpair(float v0, float v1) {
    uint32_t r; asm("cvt.rn.bf16x2.f32 %0, %1, %2;" : "=r"(r) : "f"(v1), "f"(v0)); return r;
}
__device__ __forceinline__ void hmma(float* d, const uint4& a, const uint2& b) {
    asm("mma.sync.aligned.m16n8k16.row.col.f32.bf16.bf16.f32 "
        "{%0,%1,%2,%3},{%4,%5,%6,%7},{%8,%9},{%0,%1,%2,%3};"
        : "+f"(d[0]), "+f"(d[1]), "+f"(d[2]), "+f"(d[3])
        : "r"(a.x), "r"(a.y), "r"(a.z), "r"(a.w), "r"(b.x), "r"(b.y));
}

// ---------------------------------------------------------------------------
// Prep: recurrent W -> B fragments, 64 CTAs x 64 B-cols
// (cols 0-15 Wz_hi, 16-31 Wh_hi, 32-47 Wz_lo, 48-63 Wh_lo; local hcol = j&15)
// idx = nb*32768 + ((kt*4 + nt/2)*32 + l)*4 + (nt&1)*2 + breg
// ---------------------------------------------------------------------------
__global__ void prep_bfrag(const float* __restrict__ Wz, const float* __restrict__ Wh) {
    int o = blockIdx.x * blockDim.x + threadIdx.x;   // 2097152
    int b = o & 1, l = (o >> 1) & 31, nt = (o >> 6) & 7, kt = (o >> 9) & 63, nb = o >> 15;
    int k = kt * 16 + (l & 3) * 2 + b * 8;
    int j = nt * 8 + (l >> 2);
    int hcol = nb * 16 + (j & 15);
    int kind = j >> 4;
    const float* W = (kind & 1) ? Wh : Wz;
    float w0 = W[(size_t)(512 + k) * 1024 + hcol];
    float w1 = W[(size_t)(512 + k + 1) * 1024 + hcol];
    uint32_t hi = bfpair(w0, w1);
    uint32_t val;
    if (kind < 2) val = hi;
    else {
        float r0 = w0 - __uint_as_float(hi << 16);
        float r1 = w1 - __uint_as_float(hi & 0xFFFF0000u);
        val = bfpair(r0, r1);
    }
    ((uint32_t*)g_bfrag)[(size_t)nb * 32768 + (size_t)((kt * 4 + (nt >> 1)) * 32 + l) * 4 + (nt & 1) * 2 + b] = val;
}

// emb -> hi/lo A fragments: [mt 2000][kt 32][512B]
__global__ void prep_efrag(const float* __restrict__ emb) {
    int o = blockIdx.x * blockDim.x + threadIdx.x;   // 8192000
    int j = o & 3, l = (o >> 2) & 31, kt = (o >> 7) & 31, mt = o >> 12;
    int r = mt * 16 + (j & 1) * 8 + (l >> 2);
    int k = kt * 16 + (j >> 1) * 8 + (l & 3) * 2;
    float e0 = emb[(size_t)r * EE + k];
    float e1 = emb[(size_t)r * EE + k + 1];
    uint32_t hi = bfpair(e0, e1);
    float r0 = e0 - __uint_as_float(hi << 16);
    float r1 = e1 - __uint_as_float(hi & 0xFFFF0000u);
    size_t idx = ((size_t)(mt * 32 + kt) * 32 + l) * 4 + j;
    ((uint32_t*)g_efh)[idx] = hi;
    ((uint32_t*)g_efl)[idx] = bfpair(r0, r1);
}

// Wtop -> hi/lo B fragments per col-tile
__global__ void prep_wtf(const float* __restrict__ Wz, const float* __restrict__ Wh) {
    int o = blockIdx.x * blockDim.x + threadIdx.x;   // 524288
    int j = o & 3, l = (o >> 2) & 31, ntp = (o >> 7) & 3, kt = (o >> 9) & 31, ct = o >> 14;
    int nt = ntp * 2 + (j >> 1);
    int breg = j & 1;
    int colg = ct * 64 + nt * 8 + (l >> 2);
    int k = kt * 16 + (l & 3) * 2 + breg * 8;
    const float* W = (colg < 1024) ? Wz : Wh;
    int c = colg & 1023;
    float w0 = W[(size_t)k * 1024 + c];
    float w1 = W[(size_t)(k + 1) * 1024 + c];
    uint32_t hi = bfpair(w0, w1);
    float r0 = w0 - __uint_as_float(hi << 16);
    float r1 = w1 - __uint_as_float(hi & 0xFFFF0000u);
    ((uint32_t*)g_wtfh)[o] = hi;
    ((uint32_t*)g_wtfl)[o] = bfpair(r0, r1);
}

__global__ void prep_wfc(const float* __restrict__ Wfc) {
    int o = blockIdx.x * blockDim.x + threadIdx.x;
    if (o >= 125 * 1024 * 8) return;
    int c = o & 7, k = (o >> 3) & 1023, nb = o >> 13;
    g_wfc3[o] = Wfc[(size_t)k * NC + nb * 8 + c];
}

__global__ void zero_afrag() {
    int i = blockIdx.x * blockDim.x + threadIdx.x;   // 32768 uint4
    ((uint4*)g_afrag)[i] = make_uint4(0, 0, 0, 0);
    if (i == 0) g_bar = 0u;
}

// ---------------------------------------------------------------------------
// ptable via HMMA (unchanged)
// ---------------------------------------------------------------------------
__global__ __launch_bounds__(256) void ptable_hmma(const float* __restrict__ bz,
                                                   const float* __restrict__ bh) {
    extern __shared__ char smem[];
    uint4* smh = (uint4*)smem;
    uint4* sml = (uint4*)(smem + 65536);
    const int tid = threadIdx.x, lane = tid & 31, w = tid >> 5;
    const int ct = blockIdx.x, rt = blockIdx.y;
    const int mt = rt * 8 + w;

    {
        const uint4* sh = (const uint4*)(g_wtfh + (size_t)ct * 65536);
        const uint4* sl = (const uint4*)(g_wtfl + (size_t)ct * 65536);
#pragma unroll
        for (int i = 0; i < 16; i++) {
            smh[tid + i * 256] = ldcgu4(sh + tid + i * 256);
            sml[tid + i * 256] = ldcgu4(sl + tid + i * 256);
        }
    }
    __syncthreads();

    float acc[8][4];
#pragma unroll
    for (int nt = 0; nt < 8; nt++)
#pragma unroll
        for (int j = 0; j < 4; j++) acc[nt][j] = 0.0f;

#pragma unroll 2
    for (int kt = 0; kt < 32; kt++) {
        size_t aoff = ((size_t)(mt * 32 + kt) * 32 + lane) * 16;
        uint4 ahi = ldcgu4(g_efh + aoff);
        uint4 alo = ldcgu4(g_efl + aoff);
#pragma unroll
        for (int p = 0; p < 4; p++) {
            uint4 bhv = smh[(kt * 4 + p) * 32 + lane];
            uint4 blv = sml[(kt * 4 + p) * 32 + lane];
            uint2 be = make_uint2(bhv.x, bhv.y), bo = make_uint2(bhv.z, bhv.w);
            uint2 le = make_uint2(blv.x, blv.y), lo = make_uint2(blv.z, blv.w);
            hmma(acc[2 * p], ahi, be);  hmma(acc[2 * p + 1], ahi, bo);
            hmma(acc[2 * p], alo, be);  hmma(acc[2 * p + 1], alo, bo);
            hmma(acc[2 * p], ahi, le);  hmma(acc[2 * p + 1], ahi, lo);
        }
    }

    const int gr = lane >> 2, gc = lane & 3;
    const int r0 = mt * 16 + gr, r1 = r0 + 8;
#pragma unroll
    for (int nt = 0; nt < 8; nt++) {
        int col = ct * 64 + nt * 8 + 2 * gc;
        const float* bias = (col < 1024) ? bz : bh;
        int cb = col & 1023;
        float b0 = bias[cb], b1 = bias[cb + 1];
        float2 v0 = make_float2(acc[nt][0] + b0, acc[nt][1] + b1);
        float2 v1 = make_float2(acc[nt][2] + b0, acc[nt][3] + b1);
        *(float2*)(g_pt + (size_t)r0 * 2048 + col) = v0;
        *(float2*)(g_pt + (size_t)r1 * 2048 + col) = v1;
    }
}

// ---------------------------------------------------------------------------
// Persistent HMMA recurrence v4: 64 CTAs x 256 thr (8 warps).
// warp w: kh = w>>2 (K half, 32 kt), mq = w&3 (m-tiles 2mq, 2mq+1).
// 3-product hi/lo, 24 HMMA per kt per warp. Depth-2 A prefetch (3-buffer
// rotation, ~380-cyc window > L2 262), depth-1 B LDS ping-pong. Full unroll.
// ---------------------------------------------------------------------------
#define RED_OFF 131072
#define PTS_OFF 163840
#define RECUR_SMEM_BYTES 182272

__global__ __launch_bounds__(256, 1) void recur_kernel(const int* __restrict__ x) {
    extern __shared__ char smem[];
    uint4* bs4 = (uint4*)smem;               // 128KB B fragments
    float* red = (float*)(smem + RED_OFF);   // 32KB: 4 mq x 2048 floats
    float* pts = (float*)(smem + PTS_OFF);   // 128 x 36 floats

    const int tid = threadIdx.x, lane = tid & 31, w = tid >> 5;
    const int nb = blockIdx.x;
    const int kh = w >> 2, mq = w & 3;
    const int mt0 = mq * 2, mt1 = mq * 2 + 1;
    const int gr = lane >> 2, gc = lane & 3;

    // load resident B fragments (128KB linear)
    {
        const uint4* src = (const uint4*)(g_bfrag + (size_t)nb * 131072);
#pragma unroll
        for (int i = 0; i < 32; i++) bs4[tid + i * 256] = ldcgu4(src + tid + i * 256);
    }
    __syncthreads();

    const unsigned char* aF = g_afrag;
    const size_t lo_ofs = (size_t)64 * 8 * 512;
    const unsigned abase = lane * 16;

    float hold[2][8];
#pragma unroll
    for (int m = 0; m < 2; m++)
#pragma unroll
        for (int j = 0; j < 8; j++) hold[m][j] = 0.0f;

    for (int t = 0; t < SS; t++) {
        // ---- pt staging by kh=1 warps ----
        if (kh == 1) {
            int r = mq * 32 + lane;
            int tok = __ldg(x + r * SS + t);
            const float* p = g_pt + (size_t)tok * 2048 + nb * 16;
#pragma unroll
            for (int i = 0; i < 4; i++)
                *(float4*)(pts + r * 36 + i * 4) = ldcg4(p + i * 4);
#pragma unroll
            for (int i = 0; i < 4; i++)
                *(float4*)(pts + r * 36 + 16 + i * 4) = ldcg4(p + 1024 + i * 4);
        }

        // ---- MMA phase: 768 HMMA per warp, depth-2 A pipeline ----
        float acc[2][8][4];
#pragma unroll
        for (int m = 0; m < 2; m++)
#pragma unroll
            for (int nt = 0; nt < 8; nt++)
#pragma unroll
                for (int j = 0; j < 4; j++) acc[m][nt][j] = 0.0f;

        uint4 ah[3][2], al[3][2], bq[2][4];
        {
            int k0 = kh * 32;
            ah[0][0] = ldcgu4(aF + ((size_t)k0 * 8 + mt0) * 512 + abase);
            ah[0][1] = ldcgu4(aF + ((size_t)k0 * 8 + mt1) * 512 + abase);
            al[0][0] = ldcgu4(aF + lo_ofs + ((size_t)k0 * 8 + mt0) * 512 + abase);
            al[0][1] = ldcgu4(aF + lo_ofs + ((size_t)k0 * 8 + mt1) * 512 + abase);
            ah[1][0] = ldcgu4(aF + ((size_t)(k0 + 1) * 8 + mt0) * 512 + abase);
            ah[1][1] = ldcgu4(aF + ((size_t)(k0 + 1) * 8 + mt1) * 512 + abase);
            al[1][0] = ldcgu4(aF + lo_ofs + ((size_t)(k0 + 1) * 8 + mt0) * 512 + abase);
            al[1][1] = ldcgu4(aF + lo_ofs + ((size_t)(k0 + 1) * 8 + mt1) * 512 + abase);
#pragma unroll
            for (int p = 0; p < 4; p++) bq[0][p] = bs4[(k0 * 4 + p) * 32 + lane];
        }

#pragma unroll
        for (int i = 0; i < 32; i++) {
            const int cur = i % 3;
            const int kt = kh * 32 + i;
            // prefetch A for kt+2 (two iterations ahead)
            if (i < 30) {
                const int nx = (i + 2) % 3;
                const size_t kt2 = kt + 2;
                ah[nx][0] = ldcgu4(aF + (kt2 * 8 + mt0) * 512 + abase);
                ah[nx][1] = ldcgu4(aF + (kt2 * 8 + mt1) * 512 + abase);
                al[nx][0] = ldcgu4(aF + lo_ofs + (kt2 * 8 + mt0) * 512 + abase);
                al[nx][1] = ldcgu4(aF + lo_ofs + (kt2 * 8 + mt1) * 512 + abase);
            }
            // prefetch B for kt+1 (LDS, depth-1)
            if (i < 31) {
#pragma unroll
                for (int p = 0; p < 4; p++)
                    bq[(i + 1) & 1][p] = bs4[((kt + 1) * 4 + p) * 32 + lane];
            }
            // compute kt
            const int cb = i & 1;
#pragma unroll
            for (int p = 0; p < 4; p++) {
                uint2 be = make_uint2(bq[cb][p].x, bq[cb][p].y);
                uint2 bo = make_uint2(bq[cb][p].z, bq[cb][p].w);
#pragma unroll
                for (int m = 0; m < 2; m++) {
                    hmma(acc[m][2 * p], ah[cur][m], be);
                    hmma(acc[m][2 * p + 1], ah[cur][m], bo);
                }
                if (p < 2) {
#pragma unroll
                    for (int m = 0; m < 2; m++) {
                        hmma(acc[m][2 * p], al[cur][m], be);
                        hmma(acc[m][2 * p + 1], al[cur][m], bo);
                    }
                }
            }
        }

        // ---- single reduction round: kh1 -> kh0 ----
        __syncthreads();
        if (kh == 1) {
            float* dst = red + mq * 2048;
#pragma unroll
            for (int m = 0; m < 2; m++)
#pragma unroll
                for (int nt = 0; nt < 8; nt++)
                    *(float4*)(dst + (m * 8 + nt) * 128 + lane * 4) = *(float4*)acc[m][nt];
        }
        __syncthreads();

        // ---- gates + A-fragment writeback (kh0 warps) ----
        if (kh == 0) {
            const float* src = red + mq * 2048;
#pragma unroll
            for (int m = 0; m < 2; m++) {
#pragma unroll
                for (int nt = 0; nt < 8; nt++) {
                    float4 v = *(const float4*)(src + (m * 8 + nt) * 128 + lane * 4);
                    acc[m][nt][0] += v.x; acc[m][nt][1] += v.y;
                    acc[m][nt][2] += v.z; acc[m][nt][3] += v.w;
                }
                int mtg = mq * 2 + m;
                int r0 = mtg * 16 + gr, r1 = r0 + 8;
                const float* pr0 = pts + r0 * 36;
                const float* pr1 = pts + r1 * 36;
                float hn[8];
#pragma unroll
                for (int grp = 0; grp < 2; grp++) {
                    int n0 = grp, kc = 2 * gc + grp * 8;
                    float2 pz0 = *(const float2*)(pr0 + kc);
                    float2 ph0 = *(const float2*)(pr0 + 16 + kc);
                    float2 pz1 = *(const float2*)(pr1 + kc);
                    float2 ph1 = *(const float2*)(pr1 + 16 + kc);
                    float zp[4], hp[4];
#pragma unroll
                    for (int j = 0; j < 4; j++) {
                        zp[j] = acc[m][n0][j] + acc[m][n0 + 4][j];
                        hp[j] = acc[m][n0 + 2][j] + acc[m][n0 + 6][j];
                    }
                    float pzv[4] = {pz0.x, pz0.y, pz1.x, pz1.y};
                    float phv[4] = {ph0.x, ph0.y, ph1.x, ph1.y};
#pragma unroll
                    for (int j = 0; j < 4; j++) {
                        float z = 1.0f / (1.0f + __expf(-(zp[j] + pzv[j])));
                        float th = tanhf(hp[j] + phv[j]);
                        float ho = hold[m][grp * 4 + j];
                        float v = fmaf(z, th - ho, ho);
                        hn[grp * 4 + j] = v;
                        hold[m][grp * 4 + j] = v;
                    }
                }
                uint4 hi4, lo4;
                hi4.x = bfpair(hn[0], hn[1]);
                hi4.y = bfpair(hn[2], hn[3]);
                hi4.z = bfpair(hn[4], hn[5]);
                hi4.w = bfpair(hn[6], hn[7]);
                float r00 = hn[0] - __uint_as_float(hi4.x << 16);
                float r01 = hn[1] - __uint_as_float(hi4.x & 0xFFFF0000u);
                float r10 = hn[2] - __uint_as_float(hi4.y << 16);
                float r11 = hn[3] - __uint_as_float(hi4.y & 0xFFFF0000u);
                float r20 = hn[4] - __uint_as_float(hi4.z << 16);
                float r21 = hn[5] - __uint_as_float(hi4.z & 0xFFFF0000u);
                float r30 = hn[6] - __uint_as_float(hi4.w << 16);
                float r31 = hn[7] - __uint_as_float(hi4.w & 0xFFFF0000u);
                lo4.x = bfpair(r00, r01);
                lo4.y = bfpair(r10, r11);
                lo4.z = bfpair(r20, r21);
                lo4.w = bfpair(r30, r31);
                stcgu4(g_afrag + (size_t)((nb * 8) + mtg) * 512 + lane * 16, hi4);
                stcgu4(g_afrag + (size_t)(((64 + nb) * 8) + mtg) * 512 + lane * 16, lo4);
                if (t == SS - 1) {
                    int cb2 = nb * 16 + 2 * gc;
                    g_hf[r0 * HH + cb2] = hn[0];
                    g_hf[r0 * HH + cb2 + 1] = hn[1];
                    g_hf[r1 * HH + cb2] = hn[2];
                    g_hf[r1 * HH + cb2 + 1] = hn[3];
                    g_hf[r0 * HH + cb2 + 8] = hn[4];
                    g_hf[r0 * HH + cb2 + 9] = hn[5];
                    g_hf[r1 * HH + cb2 + 8] = hn[6];
                    g_hf[r1 * HH + cb2 + 9] = hn[7];
                }
            }
        }

        // ---- grid barrier ----
        __threadfence();
        __syncthreads();
        if (tid == 0) {
            atomicAdd(&g_bar, 1u);
            unsigned target = (unsigned)(t + 1) * 64u;
            const volatile unsigned* vb = (const volatile unsigned*)&g_bar;
            while (*vb < target) {}
        }
        __syncthreads();
    }
}

// ---------------------------------------------------------------------------
// Final classifier: out[128 x 1000] = h_final @ Wfc + bfc
// ---------------------------------------------------------------------------
#define FINAL_SMEM_FLOATS (8192 + 2 * 4224 + 1152)
__global__ __launch_bounds__(256) void final_kernel(const float* __restrict__ bfc,
                                                    float* __restrict__ out) {
    extern __shared__ float sm[];
    float* ws = sm;
    float* hsm = sm + 8192;
    float* red = sm + 8192 + 2 * 4224;
    const int tid = threadIdx.x;
    const int nb = blockIdx.x;
    const int c0 = nb * 8;
    const float* hin = g_hf;
    {
        const float4* src = (const float4*)(g_wfc3 + nb * 8192);
        float4* dst = (float4*)ws;
#pragma unroll
        for (int i = 0; i < 8; i++) dst[tid + i * 256] = src[tid + i * 256];
    }
    const int r = tid & 127, kh = tid >> 7;
    ull a0 = 0, a1 = 0, a2 = 0, a3 = 0;

    for (int j = 0; j < 16; j++) {
        __syncthreads();
#pragma unroll
        for (int i = 0; i < 8; i++) {
            int idx = tid + i * 256;
            int region = idx >> 10;
            int rem = idx & 1023;
            int rr = rem >> 3;
            int kq = (rem & 7) << 2;
            float4 hv = *(const float4*)(hin + rr * HH + region * 512 + j * 32 + kq);
            float* d = hsm + region * 4224 + rr * 33 + kq;
            d[0] = hv.x; d[1] = hv.y; d[2] = hv.z; d[3] = hv.w;
        }
        __syncthreads();
        const float* hrow = hsm + kh * 4224 + r * 33;
        const ulonglong2* wp = (const ulonglong2*)(ws + (kh * 512 + j * 32) * 8);
#pragma unroll
        for (int k = 0; k < 32; k++) {
            float hv = hrow[k];
            ull hh = pack2(hv, hv);
            ulonglong2 w0 = wp[k * 2];
            ulonglong2 w1 = wp[k * 2 + 1];
            ffma2(a0, hh, w0.x);
            ffma2(a1, hh, w0.y);
            ffma2(a2, hh, w1.x);
            ffma2(a3, hh, w1.y);
        }
    }
    float v[8];
    unpack2(a0, v[0], v[1]); unpack2(a1, v[2], v[3]);
    unpack2(a2, v[4], v[5]); unpack2(a3, v[6], v[7]);
    if (kh == 1) {
#pragma unroll
        for (int c = 0; c < 8; c++) red[r * 9 + c] = v[c];
    }
    __syncthreads();
    if (kh == 0) {
#pragma unroll
        for (int c = 0; c < 8; c++)
            out[r * NC + c0 + c] = v[c] + red[r * 9 + c] + bfc[c0 + c];
    }
}

// ---------------------------------------------------------------------------
extern "C" void kernel_launch(void* const* d_in, const int* in_sizes, int n_in,
                              void* d_out, int out_size) {
    const int*   x   = (const int*)  d_in[0];
    const float* emb = (const float*)d_in[1];
    const float* Wz  = (const float*)d_in[2];
    const float* bz  = (const float*)d_in[3];
    const float* Wh  = (const float*)d_in[4];
    const float* bh  = (const float*)d_in[5];
    const float* Wfc = (const float*)d_in[6];
    const float* bfc = (const float*)d_in[7];
    float* out = (float*)d_out;
    (void)in_sizes; (void)n_in; (void)out_size;

    const int final_smem = FINAL_SMEM_FLOATS * 4;
    cudaFuncSetAttribute(recur_kernel, cudaFuncAttributeMaxDynamicSharedMemorySize, RECUR_SMEM_BYTES);
    cudaFuncSetAttribute(ptable_hmma, cudaFuncAttributeMaxDynamicSharedMemorySize, 131072);
    cudaFuncSetAttribute(final_kernel, cudaFuncAttributeMaxDynamicSharedMemorySize, final_smem);

    prep_bfrag<<<8192, 256>>>(Wz, Wh);
    prep_efrag<<<32000, 256>>>(emb);
    prep_wtf<<<2048, 256>>>(Wz, Wh);
    prep_wfc<<<(125 * 1024 * 8 + 255) / 256, 256>>>(Wfc);
    zero_afrag<<<128, 256>>>();

    ptable_hmma<<<dim3(32, 250), 256, 131072>>>(bz, bh);

    recur_kernel<<<64, 256, RECUR_SMEM_BYTES>>>(x);

    final_kernel<<<125, 256, final_smem>>>(bfc, out);
}

// round 11
// speedup vs baseline: 1.5971x; 1.5971x over previous
#include <cuda_runtime.h>
#include <cuda_bf16.h>
#include <cstdint>

#define BB 128
#define SS 512
#define EE 512
#define HH 1024
#define VV 32000
#define NC 1000

typedef unsigned long long ull;

// ---------------- global scratch ----------------
__device__ float g_pt[(size_t)VV * 2048];          // token preacts (+bias)
__device__ unsigned char g_bfrag[64 * 131072];     // per-colblock recurrent B fragments (bf16)
__device__ unsigned char g_afrag[2 * 64 * 8 * 512];// h bf16 hi/lo A fragments: [pass][kt][mt][512B]
__device__ unsigned char g_efh[(size_t)2000 * 32 * 512];  // emb hi A-fragments
__device__ unsigned char g_efl[(size_t)2000 * 32 * 512];  // emb lo A-fragments
__device__ unsigned char g_wtfh[32 * 65536];       // Wtop hi B-fragments per col-tile
__device__ unsigned char g_wtfl[32 * 65536];       // Wtop lo B-fragments per col-tile
__device__ float g_wfc3[125 * 1024 * 8];           // classifier weights per block
__device__ float g_hf[BB * HH];                    // final hidden state fp32
__device__ unsigned g_bar;                         // grid barrier counter

// ---------------- helpers ----------------
__device__ __forceinline__ ull pack2(float a, float b) {
    ull r; asm("mov.b64 %0, {%1, %2};" : "=l"(r) : "f"(a), "f"(b)); return r;
}
__device__ __forceinline__ void unpack2(ull v, float& a, float& b) {
    asm("mov.b64 {%0, %1}, %2;" : "=f"(a), "=f"(b) : "l"(v));
}
__device__ __forceinline__ void ffma2(ull& d, ull a, ull b) {
    asm("fma.rn.f32x2 %0, %1, %2, %0;" : "+l"(d) : "l"(a), "l"(b));
}
__device__ __forceinline__ float4 ldcg4(const void* p) {
    float4 v;
    asm volatile("ld.global.cg.v4.f32 {%0,%1,%2,%3},[%4];"
                 : "=f"(v.x), "=f"(v.y), "=f"(v.z), "=f"(v.w) : "l"(p));
    return v;
}
__device__ __forceinline__ uint4 ldcgu4(const void* p) {
    uint4 v;
    asm volatile("ld.global.cg.v4.b32 {%0,%1,%2,%3},[%4];"
                 : "=r"(v.x), "=r"(v.y), "=r"(v.z), "=r"(v.w) : "l"(p));
    return v;
}
__device__ __forceinline__ void stcgu4(void* p, uint4 v) {
    asm volatile("st.global.cg.v4.b32 [%0],{%1,%2,%3,%4};"
                 :: "l"(p), "r"(v.x), "r"(v.y), "r"(v.z), "r"(v.w) : "memory");
}
__device__ __forceinline__ uint32_t bfpair(float v0, float v1) {
    uint32_t r; asm("cvt.rn.bf16x2.f32 %0, %1, %2;" : "=r"(r) : "f"(v1), "f"(v0)); return r;
}
__device__ __forceinline__ void hmma(float* d, const uint4& a, const uint2& b) {
    asm("mma.sync.aligned.m16n8k16.row.col.f32.bf16.bf16.f32 "
        "{%0,%1,%2,%3},{%4,%5,%6,%7},{%8,%9},{%0,%1,%2,%3};"
        : "+f"(d[0]), "+f"(d[1]), "+f"(d[2]), "+f"(d[3])
        : "r"(a.x), "r"(a.y), "r"(a.z), "r"(a.w), "r"(b.x), "r"(b.y));
}

// ---------------------------------------------------------------------------
// Prep: recurrent W -> B fragments, 64 col-blocks x 64 B-cols
// (cols 0-15 Wz_hi, 16-31 Wh_hi, 32-47 Wz_lo, 48-63 Wh_lo; local hcol = j&15)
// idx = nb*32768 + ((kt*4 + nt/2)*32 + l)*4 + (nt&1)*2 + breg
// ---------------------------------------------------------------------------
__global__ void prep_bfrag(const float* __restrict__ Wz, const float* __restrict__ Wh) {
    int o = blockIdx.x * blockDim.x + threadIdx.x;   // 2097152
    int b = o & 1, l = (o >> 1) & 31, nt = (o >> 6) & 7, kt = (o >> 9) & 63, nb = o >> 15;
    int k = kt * 16 + (l & 3) * 2 + b * 8;
    int j = nt * 8 + (l >> 2);
    int hcol = nb * 16 + (j & 15);
    int kind = j >> 4;
    const float* W = (kind & 1) ? Wh : Wz;
    float w0 = W[(size_t)(512 + k) * 1024 + hcol];
    float w1 = W[(size_t)(512 + k + 1) * 1024 + hcol];
    uint32_t hi = bfpair(w0, w1);
    uint32_t val;
    if (kind < 2) val = hi;
    else {
        float r0 = w0 - __uint_as_float(hi << 16);
        float r1 = w1 - __uint_as_float(hi & 0xFFFF0000u);
        val = bfpair(r0, r1);
    }
    ((uint32_t*)g_bfrag)[(size_t)nb * 32768 + (size_t)((kt * 4 + (nt >> 1)) * 32 + l) * 4 + (nt & 1) * 2 + b] = val;
}

// emb -> hi/lo A fragments: [mt 2000][kt 32][512B]
__global__ void prep_efrag(const float* __restrict__ emb) {
    int o = blockIdx.x * blockDim.x + threadIdx.x;   // 8192000
    int j = o & 3, l = (o >> 2) & 31, kt = (o >> 7) & 31, mt = o >> 12;
    int r = mt * 16 + (j & 1) * 8 + (l >> 2);
    int k = kt * 16 + (j >> 1) * 8 + (l & 3) * 2;
    float e0 = emb[(size_t)r * EE + k];
    float e1 = emb[(size_t)r * EE + k + 1];
    uint32_t hi = bfpair(e0, e1);
    float r0 = e0 - __uint_as_float(hi << 16);
    float r1 = e1 - __uint_as_float(hi & 0xFFFF0000u);
    size_t idx = ((size_t)(mt * 32 + kt) * 32 + l) * 4 + j;
    ((uint32_t*)g_efh)[idx] = hi;
    ((uint32_t*)g_efl)[idx] = bfpair(r0, r1);
}

// Wtop -> hi/lo B fragments per col-tile
__global__ void prep_wtf(const float* __restrict__ Wz, const float* __restrict__ Wh) {
    int o = blockIdx.x * blockDim.x + threadIdx.x;   // 524288
    int j = o & 3, l = (o >> 2) & 31, ntp = (o >> 7) & 3, kt = (o >> 9) & 31, ct = o >> 14;
    int nt = ntp * 2 + (j >> 1);
    int breg = j & 1;
    int colg = ct * 64 + nt * 8 + (l >> 2);
    int k = kt * 16 + (l & 3) * 2 + breg * 8;
    const float* W = (colg < 1024) ? Wz : Wh;
    int c = colg & 1023;
    float w0 = W[(size_t)k * 1024 + c];
    float w1 = W[(size_t)(k + 1) * 1024 + c];
    uint32_t hi = bfpair(w0, w1);
    float r0 = w0 - __uint_as_float(hi << 16);
    float r1 = w1 - __uint_as_float(hi & 0xFFFF0000u);
    ((uint32_t*)g_wtfh)[o] = hi;
    ((uint32_t*)g_wtfl)[o] = bfpair(r0, r1);
}

__global__ void prep_wfc(const float* __restrict__ Wfc) {
    int o = blockIdx.x * blockDim.x + threadIdx.x;
    if (o >= 125 * 1024 * 8) return;
    int c = o & 7, k = (o >> 3) & 1023, nb = o >> 13;
    g_wfc3[o] = Wfc[(size_t)k * NC + nb * 8 + c];
}

__global__ void zero_afrag() {
    int i = blockIdx.x * blockDim.x + threadIdx.x;   // 32768 uint4
    ((uint4*)g_afrag)[i] = make_uint4(0, 0, 0, 0);
    if (i == 0) g_bar = 0u;
}

// ---------------------------------------------------------------------------
// ptable via HMMA (unchanged)
// ---------------------------------------------------------------------------
__global__ __launch_bounds__(256) void ptable_hmma(const float* __restrict__ bz,
                                                   const float* __restrict__ bh) {
    extern __shared__ char smem[];
    uint4* smh = (uint4*)smem;
    uint4* sml = (uint4*)(smem + 65536);
    const int tid = threadIdx.x, lane = tid & 31, w = tid >> 5;
    const int ct = blockIdx.x, rt = blockIdx.y;
    const int mt = rt * 8 + w;

    {
        const uint4* sh = (const uint4*)(g_wtfh + (size_t)ct * 65536);
        const uint4* sl = (const uint4*)(g_wtfl + (size_t)ct * 65536);
#pragma unroll
        for (int i = 0; i < 16; i++) {
            smh[tid + i * 256] = ldcgu4(sh + tid + i * 256);
            sml[tid + i * 256] = ldcgu4(sl + tid + i * 256);
        }
    }
    __syncthreads();

    float acc[8][4];
#pragma unroll
    for (int nt = 0; nt < 8; nt++)
#pragma unroll
        for (int j = 0; j < 4; j++) acc[nt][j] = 0.0f;

#pragma unroll 2
    for (int kt = 0; kt < 32; kt++) {
        size_t aoff = ((size_t)(mt * 32 + kt) * 32 + lane) * 16;
        uint4 ahi = ldcgu4(g_efh + aoff);
        uint4 alo = ldcgu4(g_efl + aoff);
#pragma unroll
        for (int p = 0; p < 4; p++) {
            uint4 bhv = smh[(kt * 4 + p) * 32 + lane];
            uint4 blv = sml[(kt * 4 + p) * 32 + lane];
            uint2 be = make_uint2(bhv.x, bhv.y), bo = make_uint2(bhv.z, bhv.w);
            uint2 le = make_uint2(blv.x, blv.y), lo = make_uint2(blv.z, blv.w);
            hmma(acc[2 * p], ahi, be);  hmma(acc[2 * p + 1], ahi, bo);
            hmma(acc[2 * p], alo, be);  hmma(acc[2 * p + 1], alo, bo);
            hmma(acc[2 * p], ahi, le);  hmma(acc[2 * p + 1], ahi, lo);
        }
    }

    const int gr = lane >> 2, gc = lane & 3;
    const int r0 = mt * 16 + gr, r1 = r0 + 8;
#pragma unroll
    for (int nt = 0; nt < 8; nt++) {
        int col = ct * 64 + nt * 8 + 2 * gc;
        const float* bias = (col < 1024) ? bz : bh;
        int cb = col & 1023;
        float b0 = bias[cb], b1 = bias[cb + 1];
        float2 v0 = make_float2(acc[nt][0] + b0, acc[nt][1] + b1);
        float2 v1 = make_float2(acc[nt][2] + b0, acc[nt][3] + b1);
        *(float2*)(g_pt + (size_t)r0 * 2048 + col) = v0;
        *(float2*)(g_pt + (size_t)r1 * 2048 + col) = v1;
    }
}

// ---------------------------------------------------------------------------
// Persistent HMMA recurrence v5: 128 CTAs x 256 thr (8 warps).
// CTA = (nb = bid>>1: 16 h-cols) x (mh = bid&1: 64 rows). Each CTA reads only
// HALF the A image (32 MB/step chip-wide vs 64). warp w: kh = w>>2 (K half),
// mq = w&3 (one m-tile mt = mh*4+mq). 384 HMMA/warp, depth-2 A prefetch.
// Fold: z = acc[n0]+acc[n0+4], ht = acc[n0+2]+acc[n0+6] (thread-local gates).
// ---------------------------------------------------------------------------
#define RED_OFF 131072
#define PTS_OFF 147456
#define RECUR_SMEM_BYTES (147456 + 64 * 36 * 4)

__global__ __launch_bounds__(256, 1) void recur_kernel(const int* __restrict__ x) {
    extern __shared__ char smem[];
    uint4* bs4 = (uint4*)smem;               // 128KB B fragments
    float* red = (float*)(smem + RED_OFF);   // 16KB: 4 mq x 1024 floats
    float* pts = (float*)(smem + PTS_OFF);   // 64 x 36 floats

    const int tid = threadIdx.x, lane = tid & 31, w = tid >> 5;
    const int bid = blockIdx.x;
    const int nb = bid >> 1, mh = bid & 1;
    const int kh = w >> 2, mq = w & 3;
    const int mt = mh * 4 + mq;              // this warp's m-tile (global 0..7)
    const int gr = lane >> 2, gc = lane & 3;

    // load resident B fragments (128KB linear; both mh CTAs load same image)
    {
        const uint4* src = (const uint4*)(g_bfrag + (size_t)nb * 131072);
#pragma unroll
        for (int i = 0; i < 32; i++) bs4[tid + i * 256] = ldcgu4(src + tid + i * 256);
    }
    __syncthreads();

    const unsigned char* aF = g_afrag;
    const size_t lo_ofs = (size_t)64 * 8 * 512;
    const unsigned abase = lane * 16;

    float hold[8];
#pragma unroll
    for (int j = 0; j < 8; j++) hold[j] = 0.0f;

    for (int t = 0; t < SS; t++) {
        // ---- pt staging by kh=1 warps: 128 thr cover 64 rows x 2 halves ----
        if (kh == 1) {
            int idx = mq * 32 + lane;
            int lr = idx >> 1, part = idx & 1;
            int rg = mh * 64 + lr;
            int tok = __ldg(x + rg * SS + t);
            const float* p = g_pt + (size_t)tok * 2048 + part * 1024 + nb * 16;
            float* d = pts + lr * 36 + part * 16;
#pragma unroll
            for (int i = 0; i < 4; i++)
                *(float4*)(d + i * 4) = ldcg4(p + i * 4);
        }

        // ---- MMA phase: 384 HMMA per warp, depth-2 A / depth-1 B pipeline ----
        float acc[8][4];
#pragma unroll
        for (int nt = 0; nt < 8; nt++)
#pragma unroll
            for (int j = 0; j < 4; j++) acc[nt][j] = 0.0f;

        uint4 ah[3], al[3], bq[2][4];
        {
            int k0 = kh * 32;
            ah[0] = ldcgu4(aF + ((size_t)k0 * 8 + mt) * 512 + abase);
            al[0] = ldcgu4(aF + lo_ofs + ((size_t)k0 * 8 + mt) * 512 + abase);
            ah[1] = ldcgu4(aF + ((size_t)(k0 + 1) * 8 + mt) * 512 + abase);
            al[1] = ldcgu4(aF + lo_ofs + ((size_t)(k0 + 1) * 8 + mt) * 512 + abase);
#pragma unroll
            for (int p = 0; p < 4; p++) bq[0][p] = bs4[(k0 * 4 + p) * 32 + lane];
        }

#pragma unroll
        for (int i = 0; i < 32; i++) {
            const int cur = i % 3;
            const int kt = kh * 32 + i;
            if (i < 30) {
                const int nx = (i + 2) % 3;
                const size_t kt2 = kt + 2;
                ah[nx] = ldcgu4(aF + (kt2 * 8 + mt) * 512 + abase);
                al[nx] = ldcgu4(aF + lo_ofs + (kt2 * 8 + mt) * 512 + abase);
            }
            if (i < 31) {
#pragma unroll
                for (int p = 0; p < 4; p++)
                    bq[(i + 1) & 1][p] = bs4[((kt + 1) * 4 + p) * 32 + lane];
            }
            const int cb = i & 1;
#pragma unroll
            for (int p = 0; p < 4; p++) {
                uint2 be = make_uint2(bq[cb][p].x, bq[cb][p].y);
                uint2 bo = make_uint2(bq[cb][p].z, bq[cb][p].w);
                hmma(acc[2 * p], ah[cur], be);
                hmma(acc[2 * p + 1], ah[cur], bo);
                if (p < 2) {
                    hmma(acc[2 * p], al[cur], be);
                    hmma(acc[2 * p + 1], al[cur], bo);
                }
            }
        }

        // ---- single reduction round: kh1 -> kh0 ----
        __syncthreads();
        if (kh == 1) {
            float* dst = red + mq * 1024;
#pragma unroll
            for (int nt = 0; nt < 8; nt++)
                *(float4*)(dst + nt * 128 + lane * 4) = *(float4*)acc[nt];
        }
        __syncthreads();

        // ---- gates + A-fragment writeback (kh0 warps) ----
        if (kh == 0) {
            const float* src = red + mq * 1024;
#pragma unroll
            for (int nt = 0; nt < 8; nt++) {
                float4 v = *(const float4*)(src + nt * 128 + lane * 4);
                acc[nt][0] += v.x; acc[nt][1] += v.y;
                acc[nt][2] += v.z; acc[nt][3] += v.w;
            }
            int lr0 = mq * 16 + gr, lr1 = lr0 + 8;    // local rows
            int r0 = mh * 64 + lr0, r1 = r0 + 8;      // global rows
            const float* pr0 = pts + lr0 * 36;
            const float* pr1 = pts + lr1 * 36;
            float hn[8];
#pragma unroll
            for (int grp = 0; grp < 2; grp++) {
                int n0 = grp, kc = 2 * gc + grp * 8;
                float2 pz0 = *(const float2*)(pr0 + kc);
                float2 ph0 = *(const float2*)(pr0 + 16 + kc);
                float2 pz1 = *(const float2*)(pr1 + kc);
                float2 ph1 = *(const float2*)(pr1 + 16 + kc);
                float zp[4], hp[4];
#pragma unroll
                for (int j = 0; j < 4; j++) {
                    zp[j] = acc[n0][j] + acc[n0 + 4][j];
                    hp[j] = acc[n0 + 2][j] + acc[n0 + 6][j];
                }
                float pzv[4] = {pz0.x, pz0.y, pz1.x, pz1.y};
                float phv[4] = {ph0.x, ph0.y, ph1.x, ph1.y};
#pragma unroll
                for (int j = 0; j < 4; j++) {
                    float z = 1.0f / (1.0f + __expf(-(zp[j] + pzv[j])));
                    float th = tanhf(hp[j] + phv[j]);
                    float ho = hold[grp * 4 + j];
                    float v = fmaf(z, th - ho, ho);
                    hn[grp * 4 + j] = v;
                    hold[grp * 4 + j] = v;
                }
            }
            uint4 hi4, lo4;
            hi4.x = bfpair(hn[0], hn[1]);
            hi4.y = bfpair(hn[2], hn[3]);
            hi4.z = bfpair(hn[4], hn[5]);
            hi4.w = bfpair(hn[6], hn[7]);
            float r00 = hn[0] - __uint_as_float(hi4.x << 16);
            float r01 = hn[1] - __uint_as_float(hi4.x & 0xFFFF0000u);
            float r10 = hn[2] - __uint_as_float(hi4.y << 16);
            float r11 = hn[3] - __uint_as_float(hi4.y & 0xFFFF0000u);
            float r20 = hn[4] - __uint_as_float(hi4.z << 16);
            float r21 = hn[5] - __uint_as_float(hi4.z & 0xFFFF0000u);
            float r30 = hn[6] - __uint_as_float(hi4.w << 16);
            float r31 = hn[7] - __uint_as_float(hi4.w & 0xFFFF0000u);
            lo4.x = bfpair(r00, r01);
            lo4.y = bfpair(r10, r11);
            lo4.z = bfpair(r20, r21);
            lo4.w = bfpair(r30, r31);
            stcgu4(g_afrag + (size_t)((nb * 8) + mt) * 512 + lane * 16, hi4);
            stcgu4(g_afrag + (size_t)(((64 + nb) * 8) + mt) * 512 + lane * 16, lo4);
            if (t == SS - 1) {
                int cb2 = nb * 16 + 2 * gc;
                g_hf[r0 * HH + cb2] = hn[0];
                g_hf[r0 * HH + cb2 + 1] = hn[1];
                g_hf[r1 * HH + cb2] = hn[2];
                g_hf[r1 * HH + cb2 + 1] = hn[3];
                g_hf[r0 * HH + cb2 + 8] = hn[4];
                g_hf[r0 * HH + cb2 + 9] = hn[5];
                g_hf[r1 * HH + cb2 + 8] = hn[6];
                g_hf[r1 * HH + cb2 + 9] = hn[7];
            }
        }

        // ---- grid barrier ----
        __threadfence();
        __syncthreads();
        if (tid == 0) {
            atomicAdd(&g_bar, 1u);
            unsigned target = (unsigned)(t + 1) * 128u;
            const volatile unsigned* vb = (const volatile unsigned*)&g_bar;
            while (*vb < target) {}
        }
        __syncthreads();
    }
}

// ---------------------------------------------------------------------------
// Final classifier: out[128 x 1000] = h_final @ Wfc + bfc
// ---------------------------------------------------------------------------
#define FINAL_SMEM_FLOATS (8192 + 2 * 4224 + 1152)
__global__ __launch_bounds__(256) void final_kernel(const float* __restrict__ bfc,
                                                    float* __restrict__ out) {
    extern __shared__ float sm[];
    float* ws = sm;
    float* hsm = sm + 8192;
    float* red = sm + 8192 + 2 * 4224;
    const int tid = threadIdx.x;
    const int nb = blockIdx.x;
    const int c0 = nb * 8;
    const float* hin = g_hf;
    {
        const float4* src = (const float4*)(g_wfc3 + nb * 8192);
        float4* dst = (float4*)ws;
#pragma unroll
        for (int i = 0; i < 8; i++) dst[tid + i * 256] = src[tid + i * 256];
    }
    const int r = tid & 127, kh = tid >> 7;
    ull a0 = 0, a1 = 0, a2 = 0, a3 = 0;

    for (int j = 0; j < 16; j++) {
        __syncthreads();
#pragma unroll
        for (int i = 0; i < 8; i++) {
            int idx = tid + i * 256;
            int region = idx >> 10;
            int rem = idx & 1023;
            int rr = rem >> 3;
            int kq = (rem & 7) << 2;
            float4 hv = *(const float4*)(hin + rr * HH + region * 512 + j * 32 + kq);
            float* d = hsm + region * 4224 + rr * 33 + kq;
            d[0] = hv.x; d[1] = hv.y; d[2] = hv.z; d[3] = hv.w;
        }
        __syncthreads();
        const float* hrow = hsm + kh * 4224 + r * 33;
        const ulonglong2* wp = (const ulonglong2*)(ws + (kh * 512 + j * 32) * 8);
#pragma unroll
        for (int k = 0; k < 32; k++) {
            float hv = hrow[k];
            ull hh = pack2(hv, hv);
            ulonglong2 w0 = wp[k * 2];
            ulonglong2 w1 = wp[k * 2 + 1];
            ffma2(a0, hh, w0.x);
            ffma2(a1, hh, w0.y);
            ffma2(a2, hh, w1.x);
            ffma2(a3, hh, w1.y);
        }
    }
    float v[8];
    unpack2(a0, v[0], v[1]); unpack2(a1, v[2], v[3]);
    unpack2(a2, v[4], v[5]); unpack2(a3, v[6], v[7]);
    if (kh == 1) {
#pragma unroll
        for (int c = 0; c < 8; c++) red[r * 9 + c] = v[c];
    }
    __syncthreads();
    if (kh == 0) {
#pragma unroll
        for (int c = 0; c < 8; c++)
            out[r * NC + c0 + c] = v[c] + red[r * 9 + c] + bfc[c0 + c];
    }
}

// ---------------------------------------------------------------------------
extern "C" void kernel_launch(void* const* d_in, const int* in_sizes, int n_in,
                              void* d_out, int out_size) {
    const int*   x   = (const int*)  d_in[0];
    const float* emb = (const float*)d_in[1];
    const float* Wz  = (const float*)d_in[2];
    const float* bz  = (const float*)d_in[3];
    const float* Wh  = (const float*)d_in[4];
    const float* bh  = (const float*)d_in[5];
    const float* Wfc = (const float*)d_in[6];
    const float* bfc = (const float*)d_in[7];
    float* out = (float*)d_out;
    (void)in_sizes; (void)n_in; (void)out_size;

    const int final_smem = FINAL_SMEM_FLOATS * 4;
    cudaFuncSetAttribute(recur_kernel, cudaFuncAttributeMaxDynamicSharedMemorySize, RECUR_SMEM_BYTES);
    cudaFuncSetAttribute(ptable_hmma, cudaFuncAttributeMaxDynamicSharedMemorySize, 131072);
    cudaFuncSetAttribute(final_kernel, cudaFuncAttributeMaxDynamicSharedMemorySize, final_smem);

    prep_bfrag<<<8192, 256>>>(Wz, Wh);
    prep_efrag<<<32000, 256>>>(emb);
    prep_wtf<<<2048, 256>>>(Wz, Wh);
    prep_wfc<<<(125 * 1024 * 8 + 255) / 256, 256>>>(Wfc);
    zero_afrag<<<128, 256>>>();

    ptable_hmma<<<dim3(32, 250), 256, 131072>>>(bz, bh);

    recur_kernel<<<128, 256, RECUR_SMEM_BYTES>>>(x);

    final_kernel<<<125, 256, final_smem>>>(bfc, out);
}